// round 1
// baseline (speedup 1.0000x reference)
#include <cuda_runtime.h>
#include <math.h>

// Problem dims
#define Tt   128
#define Bb   64
#define Ff   512
#define Hh   1024
#define NG   4096     // 4*H (gate-interleaved columns: col = 4*h + gate)
#define TBm  8192     // T*B
#define OUTF 513      // F+1
#define NKC  16       // split-K chunks for the recurrent GEMM (K=1024 -> 64 per chunk)

// ---------------- scratch (device globals; no allocations allowed) ----------
static __device__ float d_Wcat[(size_t)Ff * NG];            // 8 MB   [k][4h+g]
static __device__ float d_Ucat[(size_t)Hh * NG];            // 16 MB  [k][4h+g]
static __device__ float d_Bcat[NG];
static __device__ float d_G[(size_t)TBm * NG];              // 128 MB gate pre-activations
static __device__ float d_Hbuf[(size_t)TBm * Hh];           // 32 MB  h_t for all t
static __device__ float d_C[Bb * Hh];                       // cell state
static __device__ float d_Zpart[NKC][(size_t)Bb * NG];      // 16 MB  split-K partials

// Hamilton block tables: component index and sign per (row_block, col_block)
__constant__ int   c_CM[16] = {0,1,2,3,  1,0,3,2,  2,3,0,1,  3,2,1,0};
__constant__ float c_SG[16] = {1.f,1.f,1.f,1.f,  -1.f,1.f,1.f,-1.f,
                               -1.f,-1.f,1.f,1.f,  -1.f,1.f,-1.f,1.f};

// ---------------- build dense Hamilton matrices -----------------------------
__global__ void k_build_w(const float* __restrict__ wf, const float* __restrict__ wi,
                          const float* __restrict__ wo, const float* __restrict__ wc) {
    int idx = blockIdx.x * blockDim.x + threadIdx.x;
    if (idx >= Ff * NG) return;
    int k = idx >> 12;            // row 0..511
    int c = idx & (NG - 1);       // col
    int g  = c & 3;
    int hh = c >> 2;              // dense col 0..1023
    int cb = hh >> 8, bb = hh & 255;   // H/4 = 256
    int rb = k >> 7,  aa = k & 127;    // F/4 = 128
    const float* w = (g == 0) ? wf : (g == 1) ? wi : (g == 2) ? wo : wc;
    int m = rb * 4 + cb;
    d_Wcat[idx] = c_SG[m] * w[((size_t)c_CM[m] * 128 + aa) * 256 + bb];
}

__global__ void k_build_u(const float* __restrict__ uf, const float* __restrict__ ui,
                          const float* __restrict__ uo, const float* __restrict__ uc) {
    int idx = blockIdx.x * blockDim.x + threadIdx.x;
    if (idx >= Hh * NG) return;
    int k = idx >> 12;            // row 0..1023
    int c = idx & (NG - 1);
    int g  = c & 3;
    int hh = c >> 2;
    int cb = hh >> 8, bb = hh & 255;   // H/4 = 256
    int rb = k >> 8,  aa = k & 255;    // H/4 = 256
    const float* w = (g == 0) ? uf : (g == 1) ? ui : (g == 2) ? uo : uc;
    int m = rb * 4 + cb;
    d_Ucat[idx] = c_SG[m] * w[((size_t)c_CM[m] * 256 + aa) * 256 + bb];
}

__global__ void k_build_misc(const float* __restrict__ bf, const float* __restrict__ bi,
                             const float* __restrict__ bo, const float* __restrict__ bc) {
    int idx = blockIdx.x * blockDim.x + threadIdx.x;
    if (idx < NG) {
        int g = idx & 3, hh = idx >> 2;
        const float* b = (g == 0) ? bf : (g == 1) ? bi : (g == 2) ? bo : bc;
        d_Bcat[idx] = b[hh];
    }
    if (idx < Bb * Hh) d_C[idx] = 0.f;
    if (idx < NKC * Bb * NG) ((float*)d_Zpart)[idx] = 0.f;
}

// ---------------- input GEMM: G = x @ Wcat + Bcat  (8192x512 * 512x4096) ----
__global__ __launch_bounds__(256) void k_gemm_in(const float* __restrict__ X) {
    __shared__ __align__(16) float As[8][128];
    __shared__ __align__(16) float Bs[8][128];
    const int bn = blockIdx.x, bm = blockIdx.y;
    const int tid = threadIdx.x;
    const int tx = tid & 15, ty = tid >> 4;
    const int row0 = bm * 128, col0 = bn * 128;
    float acc[8][8];
#pragma unroll
    for (int i = 0; i < 8; i++)
#pragma unroll
        for (int j = 0; j < 8; j++) acc[i][j] = 0.f;

    const int am = tid >> 1, ak = (tid & 1) * 4;
    const int bk = tid >> 5, bn4 = (tid & 31) * 4;

    for (int k0 = 0; k0 < Ff; k0 += 8) {
        float4 av = *(const float4*)&X[(size_t)(row0 + am) * Ff + k0 + ak];
        float4 bv = *(const float4*)&d_Wcat[(size_t)(k0 + bk) * NG + col0 + bn4];
        As[ak + 0][am] = av.x; As[ak + 1][am] = av.y;
        As[ak + 2][am] = av.z; As[ak + 3][am] = av.w;
        *(float4*)&Bs[bk][bn4] = bv;
        __syncthreads();
#pragma unroll
        for (int kk = 0; kk < 8; kk++) {
            float a[8], b[8];
            *(float4*)(a)     = *(float4*)&As[kk][ty * 8];
            *(float4*)(a + 4) = *(float4*)&As[kk][ty * 8 + 4];
            *(float4*)(b)     = *(float4*)&Bs[kk][tx * 8];
            *(float4*)(b + 4) = *(float4*)&Bs[kk][tx * 8 + 4];
#pragma unroll
            for (int i = 0; i < 8; i++)
#pragma unroll
                for (int j = 0; j < 8; j++)
                    acc[i][j] = fmaf(a[i], b[j], acc[i][j]);
        }
        __syncthreads();
    }
#pragma unroll
    for (int i = 0; i < 8; i++) {
        size_t row = (size_t)(row0 + ty * 8 + i);
#pragma unroll
        for (int j = 0; j < 8; j += 4) {
            int col = col0 + tx * 8 + j;
            float4 o;
            o.x = acc[i][j]     + d_Bcat[col];
            o.y = acc[i][j + 1] + d_Bcat[col + 1];
            o.z = acc[i][j + 2] + d_Bcat[col + 2];
            o.w = acc[i][j + 3] + d_Bcat[col + 3];
            *(float4*)&d_G[row * NG + col] = o;
        }
    }
}

// ---------------- recurrent step, phase 1: split-K partial GEMM -------------
// Zpart[kc] = h_{t-1}[64, 64k-chunk] @ Ucat[chunk, 4096]; grid (32 ntiles, 16 kc)
__global__ __launch_bounds__(128) void k_step_gemm(int t) {
    __shared__ __align__(16) float Hs[16][64];
    __shared__ __align__(16) float Us[16][128];
    const float* __restrict__ Hprev = &d_Hbuf[(size_t)(t - 1) * (Bb * Hh)];
    const int col0  = blockIdx.x * 128;
    const int kc    = blockIdx.y;
    const int kbase = kc * 64;
    const int tid = threadIdx.x;
    const int tx = tid & 15, ty = tid >> 4;      // tx: col/8 (0..15), ty: batch/8 (0..7)
    float acc[8][8];
#pragma unroll
    for (int i = 0; i < 8; i++)
#pragma unroll
        for (int j = 0; j < 8; j++) acc[i][j] = 0.f;

    const int hb = tid >> 1, hk = (tid & 1) * 8;     // h: batch row, k offset
    const int uk = tid >> 3, un = (tid & 7) * 16;    // U: k row, n offset

    for (int s = 0; s < 4; s++) {
        int kb = kbase + s * 16;
        float4 h0 = *(const float4*)&Hprev[(size_t)hb * Hh + kb + hk];
        float4 h1 = *(const float4*)&Hprev[(size_t)hb * Hh + kb + hk + 4];
        const float* up = &d_Ucat[(size_t)(kb + uk) * NG + col0 + un];
        float4 u0 = *(const float4*)(up + 0);
        float4 u1 = *(const float4*)(up + 4);
        float4 u2 = *(const float4*)(up + 8);
        float4 u3 = *(const float4*)(up + 12);
        Hs[hk + 0][hb] = h0.x; Hs[hk + 1][hb] = h0.y;
        Hs[hk + 2][hb] = h0.z; Hs[hk + 3][hb] = h0.w;
        Hs[hk + 4][hb] = h1.x; Hs[hk + 5][hb] = h1.y;
        Hs[hk + 6][hb] = h1.z; Hs[hk + 7][hb] = h1.w;
        *(float4*)&Us[uk][un + 0]  = u0;
        *(float4*)&Us[uk][un + 4]  = u1;
        *(float4*)&Us[uk][un + 8]  = u2;
        *(float4*)&Us[uk][un + 12] = u3;
        __syncthreads();
#pragma unroll
        for (int kk = 0; kk < 16; kk++) {
            float a[8], b[8];
            *(float4*)(a)     = *(float4*)&Hs[kk][ty * 8];
            *(float4*)(a + 4) = *(float4*)&Hs[kk][ty * 8 + 4];
            *(float4*)(b)     = *(float4*)&Us[kk][tx * 8];
            *(float4*)(b + 4) = *(float4*)&Us[kk][tx * 8 + 4];
#pragma unroll
            for (int i = 0; i < 8; i++)
#pragma unroll
                for (int j = 0; j < 8; j++)
                    acc[i][j] = fmaf(a[i], b[j], acc[i][j]);
        }
        __syncthreads();
    }
#pragma unroll
    for (int i = 0; i < 8; i++) {
        int b = ty * 8 + i;
#pragma unroll
        for (int j = 0; j < 8; j += 4) {
            float4 o; o.x = acc[i][j]; o.y = acc[i][j + 1];
            o.z = acc[i][j + 2]; o.w = acc[i][j + 3];
            *(float4*)&d_Zpart[kc][(size_t)b * NG + col0 + tx * 8 + j] = o;
        }
    }
}

// ---------------- recurrent step, phase 2: reduce + gates + state update ----
__global__ __launch_bounds__(256) void k_step_pw(int t) {
    int idx = blockIdx.x * 256 + threadIdx.x;   // 0..65535 = b*1024 + h
    int b = idx >> 10;
    int h = idx & 1023;
    size_t zoff = (size_t)b * NG + 4 * h;
    float4 z = *(const float4*)&d_G[(size_t)t * (Bb * NG) + zoff];
#pragma unroll
    for (int kc = 0; kc < NKC; kc++) {
        float4 p = *(const float4*)&d_Zpart[kc][zoff];
        z.x += p.x; z.y += p.y; z.z += p.z; z.w += p.w;
    }
    float f  = 1.f / (1.f + expf(-z.x));
    float ig = 1.f / (1.f + expf(-z.y));
    float o  = 1.f / (1.f + expf(-z.z));
    float c = d_C[idx];
    c = ig * tanhf(z.w) + f * c;
    float hn = o * tanhf(c);
    d_C[idx] = c;
    d_Hbuf[(size_t)t * (Bb * Hh) + idx] = hn;
}

// ---------------- output GEMM: Out = Hbuf @ fco_w + fco_b  (N=513, guarded) -
__global__ __launch_bounds__(256) void k_gemm_out(const float* __restrict__ Wout,
                                                  const float* __restrict__ bout,
                                                  float* __restrict__ Out) {
    __shared__ __align__(16) float As[8][128];
    __shared__ __align__(16) float Bs[8][128];
    const int bn = blockIdx.x, bm = blockIdx.y;
    const int tid = threadIdx.x;
    const int tx = tid & 15, ty = tid >> 4;
    const int row0 = bm * 128, col0 = bn * 128;
    float acc[8][8];
#pragma unroll
    for (int i = 0; i < 8; i++)
#pragma unroll
        for (int j = 0; j < 8; j++) acc[i][j] = 0.f;

    const int am = tid >> 1, ak = (tid & 1) * 4;
    const int bk = tid >> 5, bn4 = (tid & 31) * 4;

    for (int k0 = 0; k0 < Hh; k0 += 8) {
        float4 av = *(const float4*)&d_Hbuf[(size_t)(row0 + am) * Hh + k0 + ak];
        As[ak + 0][am] = av.x; As[ak + 1][am] = av.y;
        As[ak + 2][am] = av.z; As[ak + 3][am] = av.w;
#pragma unroll
        for (int e = 0; e < 4; e++) {
            int n = col0 + bn4 + e;
            Bs[bk][bn4 + e] = (n < OUTF) ? Wout[(size_t)(k0 + bk) * OUTF + n] : 0.f;
        }
        __syncthreads();
#pragma unroll
        for (int kk = 0; kk < 8; kk++) {
            float a[8], b[8];
            *(float4*)(a)     = *(float4*)&As[kk][ty * 8];
            *(float4*)(a + 4) = *(float4*)&As[kk][ty * 8 + 4];
            *(float4*)(b)     = *(float4*)&Bs[kk][tx * 8];
            *(float4*)(b + 4) = *(float4*)&Bs[kk][tx * 8 + 4];
#pragma unroll
            for (int i = 0; i < 8; i++)
#pragma unroll
                for (int j = 0; j < 8; j++)
                    acc[i][j] = fmaf(a[i], b[j], acc[i][j]);
        }
        __syncthreads();
    }
#pragma unroll
    for (int i = 0; i < 8; i++) {
        size_t row = (size_t)(row0 + ty * 8 + i);
#pragma unroll
        for (int j = 0; j < 8; j++) {
            int col = col0 + tx * 8 + j;
            if (col < OUTF)
                Out[row * OUTF + col] = acc[i][j] + bout[col];
        }
    }
}

// ---------------- launch --------------------------------------------------
extern "C" void kernel_launch(void* const* d_in, const int* in_sizes, int n_in,
                              void* d_out, int out_size) {
    (void)in_sizes; (void)n_in; (void)out_size;
    const float* x     = (const float*)d_in[0];
    const float* wfx_w = (const float*)d_in[1];
    const float* wfx_b = (const float*)d_in[2];
    const float* wix_w = (const float*)d_in[3];
    const float* wix_b = (const float*)d_in[4];
    const float* wox_w = (const float*)d_in[5];
    const float* wox_b = (const float*)d_in[6];
    const float* wcx_w = (const float*)d_in[7];
    const float* wcx_b = (const float*)d_in[8];
    const float* ufh_w = (const float*)d_in[9];
    const float* uih_w = (const float*)d_in[10];
    const float* uoh_w = (const float*)d_in[11];
    const float* uch_w = (const float*)d_in[12];
    const float* fco_w = (const float*)d_in[13];
    const float* fco_b = (const float*)d_in[14];
    float* out = (float*)d_out;

    k_build_w<<<(Ff * NG + 255) / 256, 256>>>(wfx_w, wix_w, wox_w, wcx_w);
    k_build_u<<<(Hh * NG + 255) / 256, 256>>>(ufh_w, uih_w, uoh_w, uch_w);
    k_build_misc<<<(NKC * Bb * NG + 255) / 256, 256>>>(wfx_b, wix_b, wox_b, wcx_b);

    // G = x @ Wcat + Bcat over the whole sequence
    k_gemm_in<<<dim3(NG / 128, TBm / 128), 256>>>(x);

    // t = 0: h_{-1} = 0, Zpart already zeroed -> pointwise only
    k_step_pw<<<(Bb * Hh) / 256, 256>>>(0);
    for (int t = 1; t < Tt; t++) {
        k_step_gemm<<<dim3(NG / 128, NKC), 128>>>(t);
        k_step_pw<<<(Bb * Hh) / 256, 256>>>(t);
    }

    // Out = Hbuf @ fco_w + fco_b
    k_gemm_out<<<dim3((OUTF + 127) / 128, TBm / 128), 256>>>(fco_w, fco_b, out);
}

// round 2
// speedup vs baseline: 1.2013x; 1.2013x over previous
#include <cuda_runtime.h>
#include <math.h>

// Problem dims
#define Tt   128
#define Bb   64
#define Ff   512
#define Hh   1024
#define NG   4096     // 4*H (gate-interleaved columns: col = 4*h + gate)
#define TBm  8192     // T*B
#define OUTF 513      // F+1
#define NKC  8        // split-K chunks for the recurrent GEMM (K=1024 -> 128 per chunk)
#define NBLK 256      // persistent grid (32 ntiles x 8 kc)

// ---------------- scratch (device globals; no allocations allowed) ----------
static __device__ float d_Wcat[(size_t)Ff * NG];            // 8 MB   [k][4h+g]
static __device__ float d_Ucat[(size_t)Hh * NG];            // 16 MB  [k][4h+g]
static __device__ float d_Bcat[NG];
static __device__ float d_G[(size_t)TBm * NG];              // 128 MB gate pre-activations
static __device__ float d_Hbuf[(size_t)TBm * Hh];           // 32 MB  h_t, [t*B + b][h] (for out GEMM)
static __device__ float d_hT[(size_t)Tt * Hh * Bb];         // 32 MB  h_t transposed [t][h][b]
static __device__ float d_C[Bb * Hh];                       // cell state
static __device__ float d_Zpart[NKC][(size_t)Bb * NG];      // 8 MB  split-K partials
static __device__ unsigned g_bar;                           // grid barrier counter

// Hamilton block tables: component index and sign per (row_block, col_block)
__constant__ int   c_CM[16] = {0,1,2,3,  1,0,3,2,  2,3,0,1,  3,2,1,0};
__constant__ float c_SG[16] = {1.f,1.f,1.f,1.f,  -1.f,1.f,1.f,-1.f,
                               -1.f,-1.f,1.f,1.f,  -1.f,1.f,-1.f,1.f};

// ---------------- build dense Hamilton matrices -----------------------------
__global__ void k_build_w(const float* __restrict__ wf, const float* __restrict__ wi,
                          const float* __restrict__ wo, const float* __restrict__ wc) {
    int idx = blockIdx.x * blockDim.x + threadIdx.x;
    if (idx >= Ff * NG) return;
    int k = idx >> 12;            // row 0..511
    int c = idx & (NG - 1);       // col
    int g  = c & 3;
    int hh = c >> 2;              // dense col 0..1023
    int cb = hh >> 8, bb = hh & 255;   // H/4 = 256
    int rb = k >> 7,  aa = k & 127;    // F/4 = 128
    const float* w = (g == 0) ? wf : (g == 1) ? wi : (g == 2) ? wo : wc;
    int m = rb * 4 + cb;
    d_Wcat[idx] = c_SG[m] * w[((size_t)c_CM[m] * 128 + aa) * 256 + bb];
}

__global__ void k_build_u(const float* __restrict__ uf, const float* __restrict__ ui,
                          const float* __restrict__ uo, const float* __restrict__ uc) {
    int idx = blockIdx.x * blockDim.x + threadIdx.x;
    if (idx >= Hh * NG) return;
    int k = idx >> 12;            // row 0..1023
    int c = idx & (NG - 1);
    int g  = c & 3;
    int hh = c >> 2;
    int cb = hh >> 8, bb = hh & 255;   // H/4 = 256
    int rb = k >> 8,  aa = k & 255;    // H/4 = 256
    const float* w = (g == 0) ? uf : (g == 1) ? ui : (g == 2) ? uo : uc;
    int m = rb * 4 + cb;
    d_Ucat[idx] = c_SG[m] * w[((size_t)c_CM[m] * 256 + aa) * 256 + bb];
}

__global__ void k_build_misc(const float* __restrict__ bf, const float* __restrict__ bi,
                             const float* __restrict__ bo, const float* __restrict__ bc) {
    int idx = blockIdx.x * blockDim.x + threadIdx.x;
    if (idx == 0) g_bar = 0u;
    if (idx < NG) {
        int g = idx & 3, hh = idx >> 2;
        const float* b = (g == 0) ? bf : (g == 1) ? bi : (g == 2) ? bo : bc;
        d_Bcat[idx] = b[hh];
    }
    if (idx < Bb * Hh) d_C[idx] = 0.f;
}

// ---------------- input GEMM: G = x @ Wcat + Bcat  (8192x512 * 512x4096) ----
__global__ __launch_bounds__(256) void k_gemm_in(const float* __restrict__ X) {
    __shared__ __align__(16) float As[8][128];
    __shared__ __align__(16) float Bs[8][128];
    const int bn = blockIdx.x, bm = blockIdx.y;
    const int tid = threadIdx.x;
    const int tx = tid & 15, ty = tid >> 4;
    const int row0 = bm * 128, col0 = bn * 128;
    float acc[8][8];
#pragma unroll
    for (int i = 0; i < 8; i++)
#pragma unroll
        for (int j = 0; j < 8; j++) acc[i][j] = 0.f;

    const int am = tid >> 1, ak = (tid & 1) * 4;
    const int bk = tid >> 5, bn4 = (tid & 31) * 4;

    for (int k0 = 0; k0 < Ff; k0 += 8) {
        float4 av = *(const float4*)&X[(size_t)(row0 + am) * Ff + k0 + ak];
        float4 bv = *(const float4*)&d_Wcat[(size_t)(k0 + bk) * NG + col0 + bn4];
        As[ak + 0][am] = av.x; As[ak + 1][am] = av.y;
        As[ak + 2][am] = av.z; As[ak + 3][am] = av.w;
        *(float4*)&Bs[bk][bn4] = bv;
        __syncthreads();
#pragma unroll
        for (int kk = 0; kk < 8; kk++) {
            float a[8], b[8];
            *(float4*)(a)     = *(float4*)&As[kk][ty * 8];
            *(float4*)(a + 4) = *(float4*)&As[kk][ty * 8 + 4];
            *(float4*)(b)     = *(float4*)&Bs[kk][tx * 8];
            *(float4*)(b + 4) = *(float4*)&Bs[kk][tx * 8 + 4];
#pragma unroll
            for (int i = 0; i < 8; i++)
#pragma unroll
                for (int j = 0; j < 8; j++)
                    acc[i][j] = fmaf(a[i], b[j], acc[i][j]);
        }
        __syncthreads();
    }
#pragma unroll
    for (int i = 0; i < 8; i++) {
        size_t row = (size_t)(row0 + ty * 8 + i);
#pragma unroll
        for (int j = 0; j < 8; j += 4) {
            int col = col0 + tx * 8 + j;
            float4 o;
            o.x = acc[i][j]     + d_Bcat[col];
            o.y = acc[i][j + 1] + d_Bcat[col + 1];
            o.z = acc[i][j + 2] + d_Bcat[col + 2];
            o.w = acc[i][j + 3] + d_Bcat[col + 3];
            *(float4*)&d_G[row * NG + col] = o;
        }
    }
}

// ---------------- persistent recurrence kernel ------------------------------
__device__ __forceinline__ void grid_bar(unsigned target) {
    __syncthreads();
    if (threadIdx.x == 0) {
        __threadfence();
        atomicAdd(&g_bar, 1u);
        while (*(volatile unsigned*)&g_bar < target) { }
        __threadfence();
    }
    __syncthreads();
}

// fused split-K reduce + gates + state update for step t (all blocks share)
__device__ __forceinline__ void step_pointwise(int t, int blk, int tid) {
#pragma unroll
    for (int r = 0; r < 2; r++) {
        int e = blk * 256 + r * 128 + tid;     // 0..65535 = b*1024 + h
        int b = e >> 10;
        int h = e & 1023;
        size_t zoff = (size_t)b * NG + 4 * h;
        float4 z = *(const float4*)&d_G[(size_t)t * (Bb * NG) + zoff];
        if (t > 0) {
#pragma unroll
            for (int kc = 0; kc < NKC; kc++) {
                float4 p = __ldcg((const float4*)&d_Zpart[kc][zoff]);
                z.x += p.x; z.y += p.y; z.z += p.z; z.w += p.w;
            }
        }
        float f  = 1.f / (1.f + expf(-z.x));
        float ig = 1.f / (1.f + expf(-z.y));
        float o  = 1.f / (1.f + expf(-z.z));
        float c = d_C[e];
        c = ig * tanhf(z.w) + f * c;
        float hn = o * tanhf(c);
        d_C[e] = c;
        d_Hbuf[(size_t)t * (Bb * Hh) + e] = hn;            // [t*B+b][h] (coalesced)
        d_hT[(size_t)t * (Hh * Bb) + (size_t)h * Bb + b] = hn;  // [t][h][b]
    }
}

__global__ __launch_bounds__(128, 2) void k_recur() {
    extern __shared__ float sm[];
    float* Us = sm;               // [128][128]  U tile, resident across all steps
    float* Hs = sm + 128 * 128;   // [128][64]   h chunk for this step
    const int tid = threadIdx.x;
    const int blk = blockIdx.x;
    const int ntile = blk & 31;
    const int kc    = blk >> 5;
    const int col0  = ntile * 128;
    const int kbase = kc * 128;
    const int tx = tid & 15, ty = tid >> 4;

    // Load this block's U tile into smem ONCE (reused for all 127 steps)
#pragma unroll
    for (int i = 0; i < 32; i++) {
        int idx = tid + i * 128;
        int row = idx >> 5, n4 = (idx & 31) * 4;
        *(float4*)&Us[row * 128 + n4] =
            *(const float4*)&d_Ucat[(size_t)(kbase + row) * NG + col0 + n4];
    }

    unsigned gen = 0;

    // t = 0: h_{-1} = 0 -> Z = 0, pointwise only
    step_pointwise(0, blk, tid);
    grid_bar(++gen * NBLK);

    for (int t = 1; t < Tt; t++) {
        // ---- phase 1: Zpart[kc] = h_{t-1}[:, kchunk] @ U[kchunk, ntile] ----
        const float* hTp = &d_hT[(size_t)(t - 1) * (Hh * Bb) + (size_t)kbase * Bb];
#pragma unroll
        for (int i = 0; i < 16; i++) {
            int idx = (tid + i * 128) * 4;
            *(float4*)&Hs[idx] = *(const float4*)&hTp[idx];
        }
        __syncthreads();

        float acc[8][8];
#pragma unroll
        for (int i = 0; i < 8; i++)
#pragma unroll
            for (int j = 0; j < 8; j++) acc[i][j] = 0.f;

#pragma unroll 4
        for (int kk = 0; kk < 128; kk++) {
            float a[8], b[8];
            *(float4*)(a)     = *(float4*)&Hs[kk * 64 + ty * 8];
            *(float4*)(a + 4) = *(float4*)&Hs[kk * 64 + ty * 8 + 4];
            *(float4*)(b)     = *(float4*)&Us[kk * 128 + tx * 8];
            *(float4*)(b + 4) = *(float4*)&Us[kk * 128 + tx * 8 + 4];
#pragma unroll
            for (int i = 0; i < 8; i++)
#pragma unroll
                for (int j = 0; j < 8; j++)
                    acc[i][j] = fmaf(a[i], b[j], acc[i][j]);
        }
#pragma unroll
        for (int i = 0; i < 8; i++) {
            float* zp = &d_Zpart[kc][(size_t)(ty * 8 + i) * NG + col0 + tx * 8];
            __stcg((float4*)zp,       make_float4(acc[i][0], acc[i][1], acc[i][2], acc[i][3]));
            __stcg((float4*)(zp + 4), make_float4(acc[i][4], acc[i][5], acc[i][6], acc[i][7]));
        }
        grid_bar(++gen * NBLK);

        // ---- phase 2: reduce + gates + state update ----
        step_pointwise(t, blk, tid);
        grid_bar(++gen * NBLK);
    }
}

// ---------------- output GEMM: Out = Hbuf @ fco_w + fco_b  (N=513, guarded) -
__global__ __launch_bounds__(256) void k_gemm_out(const float* __restrict__ Wout,
                                                  const float* __restrict__ bout,
                                                  float* __restrict__ Out) {
    __shared__ __align__(16) float As[8][128];
    __shared__ __align__(16) float Bs[8][128];
    const int bn = blockIdx.x, bm = blockIdx.y;
    const int tid = threadIdx.x;
    const int tx = tid & 15, ty = tid >> 4;
    const int row0 = bm * 128, col0 = bn * 128;
    float acc[8][8];
#pragma unroll
    for (int i = 0; i < 8; i++)
#pragma unroll
        for (int j = 0; j < 8; j++) acc[i][j] = 0.f;

    const int am = tid >> 1, ak = (tid & 1) * 4;
    const int bk = tid >> 5, bn4 = (tid & 31) * 4;

    for (int k0 = 0; k0 < Hh; k0 += 8) {
        float4 av = *(const float4*)&d_Hbuf[(size_t)(row0 + am) * Hh + k0 + ak];
        As[ak + 0][am] = av.x; As[ak + 1][am] = av.y;
        As[ak + 2][am] = av.z; As[ak + 3][am] = av.w;
#pragma unroll
        for (int e = 0; e < 4; e++) {
            int n = col0 + bn4 + e;
            Bs[bk][bn4 + e] = (n < OUTF) ? Wout[(size_t)(k0 + bk) * OUTF + n] : 0.f;
        }
        __syncthreads();
#pragma unroll
        for (int kk = 0; kk < 8; kk++) {
            float a[8], b[8];
            *(float4*)(a)     = *(float4*)&As[kk][ty * 8];
            *(float4*)(a + 4) = *(float4*)&As[kk][ty * 8 + 4];
            *(float4*)(b)     = *(float4*)&Bs[kk][tx * 8];
            *(float4*)(b + 4) = *(float4*)&Bs[kk][tx * 8 + 4];
#pragma unroll
            for (int i = 0; i < 8; i++)
#pragma unroll
                for (int j = 0; j < 8; j++)
                    acc[i][j] = fmaf(a[i], b[j], acc[i][j]);
        }
        __syncthreads();
    }
#pragma unroll
    for (int i = 0; i < 8; i++) {
        size_t row = (size_t)(row0 + ty * 8 + i);
#pragma unroll
        for (int j = 0; j < 8; j++) {
            int col = col0 + tx * 8 + j;
            if (col < OUTF)
                Out[row * OUTF + col] = acc[i][j] + bout[col];
        }
    }
}

// ---------------- launch --------------------------------------------------
extern "C" void kernel_launch(void* const* d_in, const int* in_sizes, int n_in,
                              void* d_out, int out_size) {
    (void)in_sizes; (void)n_in; (void)out_size;
    const float* x     = (const float*)d_in[0];
    const float* wfx_w = (const float*)d_in[1];
    const float* wfx_b = (const float*)d_in[2];
    const float* wix_w = (const float*)d_in[3];
    const float* wix_b = (const float*)d_in[4];
    const float* wox_w = (const float*)d_in[5];
    const float* wox_b = (const float*)d_in[6];
    const float* wcx_w = (const float*)d_in[7];
    const float* wcx_b = (const float*)d_in[8];
    const float* ufh_w = (const float*)d_in[9];
    const float* uih_w = (const float*)d_in[10];
    const float* uoh_w = (const float*)d_in[11];
    const float* uch_w = (const float*)d_in[12];
    const float* fco_w = (const float*)d_in[13];
    const float* fco_b = (const float*)d_in[14];
    float* out = (float*)d_out;

    const int recurSmem = (128 * 128 + 128 * 64) * (int)sizeof(float);  // 96 KB
    cudaFuncSetAttribute(k_recur, cudaFuncAttributeMaxDynamicSharedMemorySize, recurSmem);

    k_build_w<<<(Ff * NG + 255) / 256, 256>>>(wfx_w, wix_w, wox_w, wcx_w);
    k_build_u<<<(Hh * NG + 255) / 256, 256>>>(ufh_w, uih_w, uoh_w, uch_w);
    k_build_misc<<<(Bb * Hh + 255) / 256, 256>>>(wfx_b, wix_b, wox_b, wcx_b);

    // G = x @ Wcat + Bcat over the whole sequence
    k_gemm_in<<<dim3(NG / 128, TBm / 128), 256>>>(x);

    // Entire recurrence in one persistent kernel (grid barrier between phases)
    k_recur<<<NBLK, 128, recurSmem>>>();

    // Out = Hbuf @ fco_w + fco_b
    k_gemm_out<<<dim3((OUTF + 127) / 128, TBm / 128), 256>>>(fco_w, fco_b, out);
}